// round 17
// baseline (speedup 1.0000x reference)
#include <cuda_runtime.h>
#include <cuda_fp16.h>
#include <cstdint>
#include <cstddef>

#define N_ROWS 500000
#define D_IN   128
#define R_DIM  256
#define D_OUT  64
#define U_DIM  10000
#define EPS    1e-8f
#define BM     128                     // rows per tile
#define NTHR   256                     // 8 warps, each owns 16 rows
#define NT     ((N_ROWS + BM - 1) / BM)
#define GRID_P 160                     // persistent CTAs (>=SM count; extras exit)

// ---------------- precomputed weights (fp16, [n][k] layout) -----------------
__device__ __half g_w0m[R_DIM * D_IN];            // Wmu0
__device__ __half g_w0v[R_DIM * D_IN];            // exp(Wlv0)
__device__ __half g_w1m[D_OUT * R_DIM];           // Wmu1
__device__ __half g_w1a1[D_OUT * R_DIM];          // Wmu1^2 + exp(Wlv1)
__device__ __half g_w1vh[D_OUT * R_DIM];          // exp(Wlv1)
__device__ float g_sum_inv[U_DIM * D_OUT];
__device__ float g_sum_minv[U_DIM * D_OUT];
__device__ int   g_tile_ctr;                      // work-stealing counter

// ---------------- smem layout (bytes) ---------------------------------------
#define P0B 272
#define P1B 80
#define S_STG    0                     // fp32 X staging: 128*512 = 65536
#define S_XH     65536                 // fp16 X: 128*272 = 34816
#define S_W0     100352                // 2 stages x 2 mats x 32*272 = 34816
#define W0_STAGE 17408
#define W0_MAT   8704
#define S_W1     135168                // 2 stages x 3 mats x 64*80 = 30720
#define W1_STAGE 15360
#define W1_MAT   5120
#define S_EPI    165888                // sInv staging: 128*65*4 = 33280
#define S_UID    199168                // 128*4
#define S_CTR    199680                // tile-index broadcast slot (4B + pad)
#define SMEM_SZ  199696
// sMinv staging overlays S_XH (dead after per-tile hoist)

// ---------------- helpers ----------------------------------------------------
static __device__ __forceinline__ uint32_t smem_u32(const void* p) {
    uint32_t a;
    asm("{ .reg .u64 t; cvta.to.shared.u64 t, %1; cvt.u32.u64 %0, t; }"
        : "=r"(a) : "l"(p));
    return a;
}
#define LDSM4(R, addr) \
    asm volatile("ldmatrix.sync.aligned.m8n8.x4.shared.b16 {%0,%1,%2,%3}, [%4];" \
        : "=r"((R)[0]), "=r"((R)[1]), "=r"((R)[2]), "=r"((R)[3]) : "r"(addr))
#define CP16(s, g) \
    asm volatile("cp.async.cg.shared.global [%0], [%1], 16;" :: "r"(s), "l"(g))
#define CP_COMMIT() asm volatile("cp.async.commit_group;" ::: "memory")
#define CP_WAIT(N)  asm volatile("cp.async.wait_group %0;" :: "n"(N) : "memory")

static __device__ __forceinline__ void mma16816h(float* c, const uint32_t* a,
                                                 const uint32_t* b) {
    asm volatile("mma.sync.aligned.m16n8k16.row.col.f32.f16.f16.f32 "
                 "{%0,%1,%2,%3},{%4,%5,%6,%7},{%8,%9},{%0,%1,%2,%3};"
                 : "+f"(c[0]), "+f"(c[1]), "+f"(c[2]), "+f"(c[3])
                 : "r"(a[0]), "r"(a[1]), "r"(a[2]), "r"(a[3]),
                   "r"(b[0]), "r"(b[1]));
}
static __device__ __forceinline__ uint32_t pkh(__half a, __half b) {
    return (uint32_t)__half_as_ushort(a) | ((uint32_t)__half_as_ushort(b) << 16);
}
static __device__ __forceinline__ uint32_t pkf(float a, float b) {
    return pkh(__float2half(a), __float2half(b));
}
static __device__ __forceinline__ uint32_t sq2(uint32_t u) {
    __half2 h = *reinterpret_cast<__half2*>(&u);
    h = __hmul2(h, h);
    return *reinterpret_cast<uint32_t*>(&h);
}

// ---------------- prep -------------------------------------------------------
__global__ __launch_bounds__(256) void prep_kernel(const float* __restrict__ Wmu0,
                                                   const float* __restrict__ Wlv0,
                                                   const float* __restrict__ Wmu1,
                                                   const float* __restrict__ Wlv1) {
    int id = blockIdx.x * 256 + threadIdx.x;
    if (id == 0) g_tile_ctr = 0;
    if (id < R_DIM * D_IN) {
        int n = id >> 7, k = id & 127;
        float wm = Wmu0[(size_t)k * R_DIM + n];
        float wv = expf(Wlv0[(size_t)k * R_DIM + n]);
        g_w0m[id] = __float2half(wm);
        g_w0v[id] = __float2half(wv);
    }
    if (id < D_OUT * R_DIM) {
        int n = id >> 8, k = id & 255;
        float wm = Wmu1[(size_t)k * D_OUT + n];
        float e  = expf(Wlv1[(size_t)k * D_OUT + n]);
        g_w1m[id]  = __float2half(wm);
        g_w1a1[id] = __float2half(wm * wm + e);
        g_w1vh[id] = __float2half(e);
    }
    if (id < U_DIM * D_OUT) { g_sum_inv[id] = 0.f; g_sum_minv[id] = 0.f; }
}

// ---------------- cp.async issue helpers (device) ----------------------------
static __device__ __forceinline__ void issue_X(uint32_t sb, const float* X,
                                               int tile, int t) {
    #pragma unroll
    for (int it = 0; it < 16; it++) {
        int idx = t + it * NTHR;
        int row = idx >> 5, c16 = idx & 31;
        int grow = tile * BM + row;
        if (grow < N_ROWS)
            CP16(sb + S_STG + row * 512 + c16 * 16,
                 (const char*)(X + (size_t)grow * D_IN + c16 * 4));
    }
}
static __device__ __forceinline__ void issue_W(uint32_t sb, int chunk, int stage,
                                               int t) {
    uint32_t b0 = sb + S_W0 + stage * W0_STAGE;
    #pragma unroll
    for (int it = 0; it < 2; it++) {
        int idx = t + it * NTHR;
        int r = idx >> 4, kk = idx & 15;
        size_t go = (size_t)(chunk * 32 + r) * D_IN + kk * 8;
        uint32_t so = b0 + r * P0B + kk * 16;
        CP16(so,          (const char*)&g_w0m[go]);
        CP16(so + W0_MAT, (const char*)&g_w0v[go]);
    }
    uint32_t b1 = sb + S_W1 + stage * W1_STAGE;
    int row = t >> 2, k16 = t & 3;
    size_t go = (size_t)row * R_DIM + chunk * 32 + k16 * 8;
    uint32_t so = b1 + row * P1B + k16 * 16;
    CP16(so,              (const char*)&g_w1m[go]);
    CP16(so + W1_MAT,     (const char*)&g_w1a1[go]);
    CP16(so + 2 * W1_MAT, (const char*)&g_w1vh[go]);
}

// ============================================================================
// Persistent fused kernel. One tile fetch per CTA (t0 atomicAdd, smem
// broadcast); next tile's X prefetched during current tile's MMA chunks.
//   L0 M = x*w0m,  L0 V = x2*w0v,   L1 M = m*w1m,  L1 V = v*a1 + m2*w1v.
// ============================================================================
__global__ __launch_bounds__(NTHR, 1) void fused_kernel(const float* __restrict__ X,
                                                        const int* __restrict__ X_idx) {
    extern __shared__ char sm[];
    const uint32_t sb = smem_u32(sm);
    const int t = threadIdx.x, lane = t & 31, wid = t >> 5;
    const int lr = lane & 7, sel = lane >> 3;
    int* ctr = (int*)(sm + S_CTR);

    // ---- prologue: one tile fetch per CTA, broadcast -------------------------
    if (t == 0) *ctr = atomicAdd(&g_tile_ctr, 1);
    __syncthreads();
    int cur = *ctr;
    if (cur < NT) {
        issue_X(sb, X, cur, t);
        issue_W(sb, 0, 0, t);
    }
    CP_COMMIT();

    while (cur < NT) {
        const int rowBase = cur * BM;

        CP_WAIT(0);
        __syncthreads();                 // B1: X staging + W[0] visible; prev
                                         // epilogue smem reads complete

        // ---- convert fp32 staging -> fp16 X; load uids; t0 fetches nxt --------
        #pragma unroll
        for (int it = 0; it < 16; it++) {
            int idx = t + it * NTHR;
            int row = idx >> 5, k4 = (idx & 31) * 4;
            float4 v = *(const float4*)(sm + S_STG + row * 512 + k4 * 4);
            int o = row * P0B + k4 * 2;
            *(uint32_t*)(sm + S_XH + o)     = pkf(v.x, v.y);
            *(uint32_t*)(sm + S_XH + o + 4) = pkf(v.z, v.w);
        }
        if (t < BM) {
            int r = rowBase + t;
            *(int*)(sm + S_UID + t * 4) = (r < N_ROWS) ? X_idx[r] : -1;
        }
        if (t == 0) *ctr = atomicAdd(&g_tile_ctr, 1);
        __syncthreads();                 // B2: fp16 X + uids + nxt visible
        const int nxt = *ctr;

        // ---- hoist X fragments into registers; square in registers -----------
        uint32_t Ax[8][4], A2[8][4];
        #pragma unroll
        for (int ks = 0; ks < 8; ks++) {
            int ar = wid * 16 + lr + (sel & 1) * 8;
            int ac = ks * 16 + (sel >> 1) * 8;
            LDSM4(Ax[ks], sb + S_XH + (uint32_t)(ar * P0B + ac * 2));
            #pragma unroll
            for (int e = 0; e < 4; e++) A2[ks][e] = sq2(Ax[ks][e]);
        }

        // ---- prefetch NEXT tile's X (overlaps all 8 chunks) -------------------
        if (nxt < NT) issue_X(sb, X, nxt, t);
        CP_COMMIT();

        float acc1M[8][4], acc1V[8][4];
        #pragma unroll
        for (int b = 0; b < 8; b++)
            #pragma unroll
            for (int c = 0; c < 4; c++) { acc1M[b][c] = 0.f; acc1V[b][c] = 0.f; }

        for (int nc = 0; nc < 8; nc++) {
            if (nc) { CP_WAIT(0); __syncthreads(); }   // W[nc] arrived+visible

            // issue W[nc+1] (nc==7 -> next tile's W[0] into stage 0)
            issue_W(sb, (nc + 1) & 7, (nc + 1) & 1, t);
            CP_COMMIT();

            const uint32_t w0b = sb + S_W0 + (nc & 1) * W0_STAGE;
            const uint32_t w1b = sb + S_W1 + (nc & 1) * W1_STAGE;

            // ---- layer0: 16(m) x 32(n), K=128, A in registers -----------------
            float a0M[4][4], a0V[4][4];
            #pragma unroll
            for (int b = 0; b < 4; b++)
                #pragma unroll
                for (int c = 0; c < 4; c++) { a0M[b][c] = 0.f; a0V[b][c] = 0.f; }

            #pragma unroll
            for (int ks = 0; ks < 8; ks++) {
                const int k = ks * 16;
                #pragma unroll
                for (int g = 0; g < 2; g++) {
                    uint32_t Bm[4], Bv[4];
                    int br = g * 16 + lr + (sel >> 1) * 8;
                    int bc = k + (sel & 1) * 8;
                    uint32_t off = (uint32_t)(br * P0B + bc * 2);
                    LDSM4(Bm, w0b + off);
                    LDSM4(Bv, w0b + W0_MAT + off);
                    #pragma unroll
                    for (int q = 0; q < 2; q++) {
                        int n8 = g * 2 + q;
                        mma16816h(a0M[n8], Ax[ks], &Bm[q * 2]);
                        mma16816h(a0V[n8], A2[ks], &Bv[q * 2]);
                    }
                }
            }

            // ---- gate + square + repack C -> layer1 A fragments ----------------
            uint32_t Am[2][4], Av[2][4], A2m[2][4];
            #pragma unroll
            for (int n8 = 0; n8 < 4; n8++) {
                float gm[4], gv[4];
                #pragma unroll
                for (int e = 0; e < 4; e++) {
                    float m = a0M[n8][e];
                    bool g = m > 0.f;
                    gm[e] = g ? m : 0.f;
                    gv[e] = g ? a0V[n8][e] : 0.f;
                }
                int ko = n8 >> 1, hi = (n8 & 1) * 2;
                Am[ko][hi]      = pkf(gm[0], gm[1]);
                Am[ko][hi + 1]  = pkf(gm[2], gm[3]);
                Av[ko][hi]      = pkf(gv[0], gv[1]);
                Av[ko][hi + 1]  = pkf(gv[2], gv[3]);
                A2m[ko][hi]     = pkf(gm[0] * gm[0], gm[1] * gm[1]);
                A2m[ko][hi + 1] = pkf(gm[2] * gm[2], gm[3] * gm[3]);
            }

            // ---- layer1: 16(m) x 64(n), K=32, A in registers -------------------
            #pragma unroll
            for (int ko = 0; ko < 2; ko++) {
                #pragma unroll
                for (int g = 0; g < 4; g++) {
                    uint32_t Bm[4], Ba[4], Bv[4];
                    int br = g * 16 + lr + (sel >> 1) * 8;
                    int bc = ko * 16 + (sel & 1) * 8;
                    uint32_t off = (uint32_t)(br * P1B + bc * 2);
                    LDSM4(Bm, w1b + off);
                    LDSM4(Ba, w1b + W1_MAT + off);
                    LDSM4(Bv, w1b + 2 * W1_MAT + off);
                    #pragma unroll
                    for (int q = 0; q < 2; q++) {
                        int n8 = g * 2 + q;
                        mma16816h(acc1M[n8], Am[ko], &Bm[q * 2]);
                        mma16816h(acc1V[n8], Av[ko], &Ba[q * 2]);
                        mma16816h(acc1V[n8], A2m[ko], &Bv[q * 2]);
                    }
                }
            }
        }

        // ---- epilogue: inv-variance weighting into smem staging ----------------
        float* sInv  = (float*)(sm + S_EPI);
        float* sMinv = (float*)(sm + S_XH);     // fp16 X region dead post-hoist
        #pragma unroll
        for (int n8 = 0; n8 < 8; n8++) {
            int col = n8 * 8 + 2 * (lane & 3);
            #pragma unroll
            for (int half = 0; half < 2; half++) {
                int lrow = wid * 16 + (lane >> 2) + half * 8;
                float m0 = acc1M[n8][half * 2 + 0];
                float m1 = acc1M[n8][half * 2 + 1];
                float V0 = fmaxf(acc1V[n8][half * 2 + 0], EPS);
                float V1 = fmaxf(acc1V[n8][half * 2 + 1], EPS);
                float i0 = 1.f / V0, i1 = 1.f / V1;
                sInv[lrow * 65 + col]      = i0;
                sInv[lrow * 65 + col + 1]  = i1;
                sMinv[lrow * 65 + col]     = m0 * i0;
                sMinv[lrow * 65 + col + 1] = m1 * i1;
            }
        }
        __syncthreads();

        // ---- block-level segmented reduce over sorted uids -> atomics ----------
        const int* uids = (const int*)(sm + S_UID);
        int col = t & 63, grp = t >> 6;          // 4 groups x 32 rows
        float aI = 0.f, aM = 0.f;
        int curUid = -1;
        for (int r0 = 0; r0 < 32; r0++) {
            int row = grp * 32 + r0;
            int uid = uids[row];
            if (uid != curUid) {
                if (curUid >= 0) {
                    atomicAdd(&g_sum_inv[curUid * D_OUT + col], aI);
                    atomicAdd(&g_sum_minv[curUid * D_OUT + col], aM);
                }
                curUid = uid; aI = 0.f; aM = 0.f;
            }
            if (uid >= 0) {
                aI += sInv[row * 65 + col];
                aM += sMinv[row * 65 + col];
            }
        }
        if (curUid >= 0) {
            atomicAdd(&g_sum_inv[curUid * D_OUT + col], aI);
            atomicAdd(&g_sum_minv[curUid * D_OUT + col], aM);
        }

        cur = nxt;
    }
    CP_WAIT(0);                          // drain any outstanding prefetches
}

// ---------------- finalize ----------------------------------------------------
__global__ __launch_bounds__(256) void finalize_kernel(float* __restrict__ out) {
    int id = blockIdx.x * 256 + threadIdx.x;
    if (id < U_DIM * D_OUT) {
        float var = 1.f / (g_sum_inv[id] + EPS);
        out[id]                 = g_sum_minv[id] * var;
        out[U_DIM * D_OUT + id] = var;
    }
}

// ---------------- launch -------------------------------------------------------
extern "C" void kernel_launch(void* const* d_in, const int* in_sizes, int n_in,
                              void* d_out, int out_size) {
    const float* X     = (const float*)d_in[0];
    const int*   X_idx = (const int*)d_in[1];
    const float* Wmu0  = (const float*)d_in[2];
    const float* Wlv0  = (const float*)d_in[3];
    const float* Wmu1  = (const float*)d_in[4];
    const float* Wlv1  = (const float*)d_in[5];
    float* out = (float*)d_out;
    (void)in_sizes; (void)n_in; (void)out_size;

    cudaFuncSetAttribute(fused_kernel, cudaFuncAttributeMaxDynamicSharedMemorySize,
                         SMEM_SZ);

    prep_kernel<<<(U_DIM * D_OUT + 255) / 256, 256>>>(Wmu0, Wlv0, Wmu1, Wlv1);
    fused_kernel<<<GRID_P, NTHR, SMEM_SZ>>>(X, X_idx);
    finalize_kernel<<<(U_DIM * D_OUT + 255) / 256, 256>>>(out);
}